// round 2
// baseline (speedup 1.0000x reference)
#include <cuda_runtime.h>
#include <cstdint>
#include <cstddef>

// Problem constants
#define BATCH 256
#define SEQ   512
#define INDIM 32
#define H0 64
#define H1 128
#define H2 256

// ---------------- scratch (no allocations allowed) ----------------
__device__ float g_pre [(size_t)BATCH * SEQ * 4 * H2];   // 512 MB, reused per layer
__device__ float g_x1  [(size_t)BATCH * SEQ * H0];
__device__ float g_x2  [(size_t)BATCH * SEQ * H1];
__device__ float g_x3  [(size_t)BATCH * SEQ * H2];
__device__ float g_hbuf[2 * BATCH * H2];                 // double-buffered h exchange
__device__ unsigned int g_ctr[128 * 32];                 // padded group counters

__device__ __forceinline__ float sigf(float x)  { return 1.f / (1.f + __expf(-x)); }
__device__ __forceinline__ float tanhfast(float x) { return 2.f / (1.f + __expf(-2.f * x)) - 1.f; }

// ---------------- counter reset (runs each replay) ----------------
__global__ void init_ctr_kernel(unsigned int* c) {
    c[blockIdx.x * 256 + threadIdx.x] = 0u;
}

// ---------------- input GEMM: C[M,N] = X[M,K] @ W[N,K]^T + bih + bhh ----------------
// M = BATCH*SEQ = 131072. BM=128, BN=64, BK=32, 256 threads, 8x4 per thread.
template <int K, int N>
__global__ void __launch_bounds__(256) gemm_pre_kernel(
    const float* __restrict__ X, const float* __restrict__ W,
    const float* __restrict__ bih, const float* __restrict__ bhh,
    float* __restrict__ C)
{
    constexpr int BM = 128, BN = 64, BK = 32;
    __shared__ float Xs[BK * BM];
    __shared__ float Wt[BK * BN];

    const int m0 = blockIdx.x * BM;
    const int n0 = blockIdx.y * BN;
    const int tid = threadIdx.x;

    float acc[8][4];
#pragma unroll
    for (int i = 0; i < 8; i++)
#pragma unroll
        for (int j = 0; j < 4; j++) acc[i][j] = 0.f;

    const int tm = (tid >> 4) << 3;   // 0..120
    const int tn = (tid & 15) << 2;   // 0..60

    for (int k0 = 0; k0 < K; k0 += BK) {
        // load X tile [BM][BK] -> Xs[k][m]
#pragma unroll
        for (int i = 0; i < 4; i++) {
            int f4  = tid + i * 256;          // 0..1023
            int row = f4 >> 3;
            int kk  = (f4 & 7) << 2;
            float4 v = *reinterpret_cast<const float4*>(&X[(size_t)(m0 + row) * K + k0 + kk]);
            Xs[(kk + 0) * BM + row] = v.x;
            Xs[(kk + 1) * BM + row] = v.y;
            Xs[(kk + 2) * BM + row] = v.z;
            Xs[(kk + 3) * BM + row] = v.w;
        }
        // load W tile [BN][BK] -> Wt[k][n]
#pragma unroll
        for (int i = 0; i < 2; i++) {
            int f4  = tid + i * 256;          // 0..511
            int row = f4 >> 3;
            int kk  = (f4 & 7) << 2;
            float4 v = *reinterpret_cast<const float4*>(&W[(size_t)(n0 + row) * K + k0 + kk]);
            Wt[(kk + 0) * BN + row] = v.x;
            Wt[(kk + 1) * BN + row] = v.y;
            Wt[(kk + 2) * BN + row] = v.z;
            Wt[(kk + 3) * BN + row] = v.w;
        }
        __syncthreads();

#pragma unroll
        for (int kk = 0; kk < BK; kk++) {
            float4 a0 = *reinterpret_cast<const float4*>(&Xs[kk * BM + tm]);
            float4 a1 = *reinterpret_cast<const float4*>(&Xs[kk * BM + tm + 4]);
            float4 b  = *reinterpret_cast<const float4*>(&Wt[kk * BN + tn]);
            float a[8] = {a0.x, a0.y, a0.z, a0.w, a1.x, a1.y, a1.z, a1.w};
            float bb[4] = {b.x, b.y, b.z, b.w};
#pragma unroll
            for (int i = 0; i < 8; i++)
#pragma unroll
                for (int j = 0; j < 4; j++) acc[i][j] += a[i] * bb[j];
        }
        __syncthreads();
    }

    float4 bias;
    bias.x = bih[n0 + tn + 0] + bhh[n0 + tn + 0];
    bias.y = bih[n0 + tn + 1] + bhh[n0 + tn + 1];
    bias.z = bih[n0 + tn + 2] + bhh[n0 + tn + 2];
    bias.w = bih[n0 + tn + 3] + bhh[n0 + tn + 3];
#pragma unroll
    for (int i = 0; i < 8; i++) {
        float4 o;
        o.x = acc[i][0] + bias.x;
        o.y = acc[i][1] + bias.y;
        o.z = acc[i][2] + bias.z;
        o.w = acc[i][3] + bias.w;
        *reinterpret_cast<float4*>(&C[(size_t)(m0 + tm + i) * N + n0 + tn]) = o;
    }
}

// ---------------- LSTM recurrence ----------------
// Grid: G * (BATCH/NB) blocks of 128 threads. Block (grp, sl) owns batches
// [grp*NB, grp*NB+NB) and hidden units [sl*JS, sl*JS+JS) (all 4 gates).
// Whh slice (transposed [k][r]) lives in SMEM for all SEQ steps.
// For G>1, h is exchanged via double-buffered global hbuf + per-group spin barrier.
template <int H, int G, int NB, int BB>
__global__ void __launch_bounds__(128) lstm_recur_kernel(
    const float* __restrict__ pre, const float* __restrict__ Whh,
    float* __restrict__ xout, float* __restrict__ hbuf,
    unsigned int* __restrict__ ctr)
{
    constexpr int R   = 4 * H / G;   // local gate rows
    constexpr int JS  = H / G;       // local hidden units
    constexpr int RB  = 4;
    constexpr int NRG = R / RB;
    constexpr int NBG = NB / BB;
    static_assert(NRG * NBG == 128, "thread mapping");
    static_assert(JS % RB == 0, "rows stay within one gate");

    extern __shared__ float sm[];
    float* Ws = sm;                       // [H][R]
    float* hs = Ws + H * R;               // [NB][H]
    float* cs = hs + NB * H;              // [NB][JS]
    float* gs = cs + NB * JS;             // [NB][R]

    const int tid = threadIdx.x;
    const int blk = blockIdx.x;
    const int grp = blk / G;
    const int sl  = blk % G;
    const int b0  = grp * NB;
    const int j0  = sl * JS;

    // load weight slice, transposed
    for (int idx = tid; idx < R * H; idx += 128) {
        int r = idx / H, k = idx - (idx / H) * H;
        int gate = r / JS, jj = r - gate * JS;
        Ws[k * R + r] = Whh[(size_t)(gate * H + j0 + jj) * H + k];
    }
    for (int idx = tid; idx < NB * H; idx += 128) hs[idx] = 0.f;
    for (int idx = tid; idx < NB * JS; idx += 128) cs[idx] = 0.f;
    __syncthreads();

    const int rg = tid % NRG, bg = tid / NRG;
    const int rbase = rg * RB, bbase = bg * BB;
    const int gate = rbase / JS, jj = rbase - gate * JS;
    const int grow = gate * H + j0 + jj;     // 4 consecutive global gate rows

    unsigned int* myctr = &ctr[grp * 32];

    for (int t = 0; t < SEQ; t++) {
        float acc[BB][RB];
#pragma unroll
        for (int b = 0; b < BB; b++) {
            float4 p = *reinterpret_cast<const float4*>(
                &pre[((size_t)(b0 + bbase + b) * SEQ + t) * (4 * H) + grow]);
            acc[b][0] = p.x; acc[b][1] = p.y; acc[b][2] = p.z; acc[b][3] = p.w;
        }
        // dot over H
#pragma unroll 2
        for (int k = 0; k < H; k += 4) {
            float4 h4[BB];
#pragma unroll
            for (int b = 0; b < BB; b++)
                h4[b] = *reinterpret_cast<const float4*>(&hs[(bbase + b) * H + k]);
#pragma unroll
            for (int kk = 0; kk < 4; kk++) {
                float4 w = *reinterpret_cast<const float4*>(&Ws[(k + kk) * R + rbase]);
#pragma unroll
                for (int b = 0; b < BB; b++) {
                    const float* hp = reinterpret_cast<const float*>(&h4[b]);
                    float hv = hp[kk];
                    acc[b][0] += hv * w.x;
                    acc[b][1] += hv * w.y;
                    acc[b][2] += hv * w.z;
                    acc[b][3] += hv * w.w;
                }
            }
        }
#pragma unroll
        for (int b = 0; b < BB; b++) {
            float4 o = {acc[b][0], acc[b][1], acc[b][2], acc[b][3]};
            *reinterpret_cast<float4*>(&gs[(bbase + b) * R + rbase]) = o;
        }
        __syncthreads();

        // activations + state update (each thread: NB*JS/128 hidden units)
        for (int idx = tid; idx < NB * JS; idx += 128) {
            int b = idx / JS, j = idx - (idx / JS) * JS;
            float gi = gs[b * R + 0 * JS + j];
            float gf = gs[b * R + 1 * JS + j];
            float gg = gs[b * R + 2 * JS + j];
            float go = gs[b * R + 3 * JS + j];
            float c = sigf(gf) * cs[idx] + sigf(gi) * tanhfast(gg);
            cs[idx] = c;
            float h = sigf(go) * tanhfast(c);
            xout[((size_t)(b0 + b) * SEQ + t) * H + j0 + j] = h;
            if (G > 1)
                hbuf[((t + 1) & 1) * (BATCH * H) + (size_t)(b0 + b) * H + j0 + j] = h;
            else
                hs[b * H + j] = h;
        }

        if (G > 1) {
            __threadfence();          // release h-slice writes
            __syncthreads();
            if (tid == 0) {
                atomicAdd(myctr, 1u);
                unsigned int target = (unsigned int)G * (unsigned int)(t + 1);
                while (*(volatile unsigned int*)myctr < target) { }
            }
            __syncthreads();
            __threadfence();          // acquire (flushes L1 so peer h is fresh)
            // stage full h for next step
            for (int idx = tid; idx < NB * H; idx += 128)
                hs[idx] = hbuf[((t + 1) & 1) * (BATCH * H) + (size_t)b0 * H + idx];
            __syncthreads();
        } else {
            __syncthreads();
        }
    }
}

// ---------------- final linear (OUT_DIM=1) + tanh ----------------
__global__ void __launch_bounds__(256) final_kernel(
    const float* __restrict__ x3, const float* __restrict__ Wl,
    const float* __restrict__ bl, float* __restrict__ out)
{
    int warp = (blockIdx.x * 256 + threadIdx.x) >> 5;
    int lane = threadIdx.x & 31;
    const float* xr = x3 + (size_t)warp * H2;
    float acc = 0.f;
#pragma unroll
    for (int i = 0; i < 8; i++) {
        int k = i * 32 + lane;
        acc += xr[k] * __ldg(&Wl[k]);
    }
#pragma unroll
    for (int off = 16; off; off >>= 1) acc += __shfl_xor_sync(0xffffffffu, acc, off);
    if (lane == 0) out[warp] = tanhf(acc + bl[0]);
}

// ---------------- launch ----------------
extern "C" void kernel_launch(void* const* d_in, const int* in_sizes, int n_in,
                              void* d_out, int out_size)
{
    const float* noise = (const float*)d_in[0];
    const float* Wih0 = (const float*)d_in[1];
    const float* Whh0 = (const float*)d_in[2];
    const float* bih0 = (const float*)d_in[3];
    const float* bhh0 = (const float*)d_in[4];
    const float* Wih1 = (const float*)d_in[5];
    const float* Whh1 = (const float*)d_in[6];
    const float* bih1 = (const float*)d_in[7];
    const float* bhh1 = (const float*)d_in[8];
    const float* Wih2 = (const float*)d_in[9];
    const float* Whh2 = (const float*)d_in[10];
    const float* bih2 = (const float*)d_in[11];
    const float* bhh2 = (const float*)d_in[12];
    const float* Wl   = (const float*)d_in[13];
    const float* bl   = (const float*)d_in[14];
    float* out = (float*)d_out;

    float *pre, *x1, *x2, *x3, *hbuf;
    unsigned int* ctr;
    cudaGetSymbolAddress((void**)&pre,  g_pre);
    cudaGetSymbolAddress((void**)&x1,   g_x1);
    cudaGetSymbolAddress((void**)&x2,   g_x2);
    cudaGetSymbolAddress((void**)&x3,   g_x3);
    cudaGetSymbolAddress((void**)&hbuf, g_hbuf);
    cudaGetSymbolAddress((void**)&ctr,  g_ctr);

    // dynamic smem sizes (bytes)
    const int smem0 = (H0 * 4 * H0 / 1 + 2 * H0 + 2 * (H0 / 1) + 2 * (4 * H0 / 1)) * 4;   // ~67KB
    const int smem1 = (H1 * 4 * H1 / 2 + 4 * H1 + 4 * (H1 / 2) + 4 * (4 * H1 / 2)) * 4;   // ~135KB
    const int smem2 = (H2 * 4 * H2 / 8 + 16 * H2 + 16 * (H2 / 8) + 16 * (4 * H2 / 8)) * 4; // ~154KB

    cudaFuncSetAttribute(lstm_recur_kernel<H0, 1, 2, 1>,
                         cudaFuncAttributeMaxDynamicSharedMemorySize, smem0);
    cudaFuncSetAttribute(lstm_recur_kernel<H1, 2, 4, 2>,
                         cudaFuncAttributeMaxDynamicSharedMemorySize, smem1);
    cudaFuncSetAttribute(lstm_recur_kernel<H2, 8, 16, 4>,
                         cudaFuncAttributeMaxDynamicSharedMemorySize, smem2);

    const int MBLK = (BATCH * SEQ) / 128;  // 1024

    init_ctr_kernel<<<16, 256>>>(ctr);

    // Layer 0
    gemm_pre_kernel<INDIM, 4 * H0><<<dim3(MBLK, (4 * H0) / 64), 256>>>(noise, Wih0, bih0, bhh0, pre);
    lstm_recur_kernel<H0, 1, 2, 1><<<128, 128, smem0>>>(pre, Whh0, x1, hbuf, ctr);

    // Layer 1
    gemm_pre_kernel<H0, 4 * H1><<<dim3(MBLK, (4 * H1) / 64), 256>>>(x1, Wih1, bih1, bhh1, pre);
    lstm_recur_kernel<H1, 2, 4, 2><<<128, 128, smem1>>>(pre, Whh1, x2, hbuf, ctr);

    // Layer 2
    gemm_pre_kernel<H1, 4 * H2><<<dim3(MBLK, (4 * H2) / 64), 256>>>(x2, Wih2, bih2, bhh2, pre);
    lstm_recur_kernel<H2, 8, 16, 4><<<128, 128, smem2>>>(pre, Whh2, x3, hbuf, ctr + 64 * 32);

    // Final linear + tanh
    final_kernel<<<(BATCH * SEQ) / 8, 256>>>(x3, Wl, bl, out);
}

// round 3
// speedup vs baseline: 1.0587x; 1.0587x over previous
#include <cuda_runtime.h>
#include <cstdint>
#include <cstddef>

// Problem constants
#define BATCH 256
#define SEQ   512
#define INDIM 32
#define H0 64
#define H1 128
#define H2 256

// ---------------- scratch (no allocations allowed) ----------------
__device__ float g_pre [(size_t)BATCH * SEQ * 4 * H2];   // 512 MB, reused per layer
__device__ float g_x1  [(size_t)BATCH * SEQ * H0];
__device__ float g_x2  [(size_t)BATCH * SEQ * H1];
__device__ float g_x3  [(size_t)BATCH * SEQ * H2];

__device__ __forceinline__ float sigf(float x)  { return 1.f / (1.f + __expf(-x)); }
__device__ __forceinline__ float tanhfast(float x) { return 2.f / (1.f + __expf(-2.f * x)) - 1.f; }

__device__ __forceinline__ uint32_t smem_u32(const void* p) {
    return (uint32_t)__cvta_generic_to_shared(p);
}
__device__ __forceinline__ void st_cluster_f32(uint32_t la, unsigned rank, float v) {
    uint32_t ra;
    asm volatile("mapa.shared::cluster.u32 %0, %1, %2;" : "=r"(ra) : "r"(la), "r"(rank));
    asm volatile("st.shared::cluster.f32 [%0], %1;" :: "r"(ra), "f"(v) : "memory");
}
__device__ __forceinline__ void cluster_sync_() {
    asm volatile("barrier.cluster.arrive.aligned;" ::: "memory");
    asm volatile("barrier.cluster.wait.aligned;" ::: "memory");
}

// ---------------- input GEMM: C[M,N] = X[M,K] @ W[N,K]^T + bih + bhh ----------------
// M = BATCH*SEQ = 131072. BM=128, BN=64, BK=32, 256 threads, 8x4 per thread.
template <int K, int N>
__global__ void __launch_bounds__(256) gemm_pre_kernel(
    const float* __restrict__ X, const float* __restrict__ W,
    const float* __restrict__ bih, const float* __restrict__ bhh,
    float* __restrict__ C)
{
    constexpr int BM = 128, BN = 64, BK = 32;
    __shared__ float Xs[BK * BM];
    __shared__ float Wt[BK * BN];

    const int m0 = blockIdx.x * BM;
    const int n0 = blockIdx.y * BN;
    const int tid = threadIdx.x;

    float acc[8][4];
#pragma unroll
    for (int i = 0; i < 8; i++)
#pragma unroll
        for (int j = 0; j < 4; j++) acc[i][j] = 0.f;

    const int tm = (tid >> 4) << 3;   // 0..120
    const int tn = (tid & 15) << 2;   // 0..60

    for (int k0 = 0; k0 < K; k0 += BK) {
#pragma unroll
        for (int i = 0; i < 4; i++) {
            int f4  = tid + i * 256;
            int row = f4 >> 3;
            int kk  = (f4 & 7) << 2;
            float4 v = *reinterpret_cast<const float4*>(&X[(size_t)(m0 + row) * K + k0 + kk]);
            Xs[(kk + 0) * BM + row] = v.x;
            Xs[(kk + 1) * BM + row] = v.y;
            Xs[(kk + 2) * BM + row] = v.z;
            Xs[(kk + 3) * BM + row] = v.w;
        }
#pragma unroll
        for (int i = 0; i < 2; i++) {
            int f4  = tid + i * 256;
            int row = f4 >> 3;
            int kk  = (f4 & 7) << 2;
            float4 v = *reinterpret_cast<const float4*>(&W[(size_t)(n0 + row) * K + k0 + kk]);
            Wt[(kk + 0) * BN + row] = v.x;
            Wt[(kk + 1) * BN + row] = v.y;
            Wt[(kk + 2) * BN + row] = v.z;
            Wt[(kk + 3) * BN + row] = v.w;
        }
        __syncthreads();

#pragma unroll
        for (int kk = 0; kk < BK; kk++) {
            float4 a0 = *reinterpret_cast<const float4*>(&Xs[kk * BM + tm]);
            float4 a1 = *reinterpret_cast<const float4*>(&Xs[kk * BM + tm + 4]);
            float4 b  = *reinterpret_cast<const float4*>(&Wt[kk * BN + tn]);
            float a[8] = {a0.x, a0.y, a0.z, a0.w, a1.x, a1.y, a1.z, a1.w};
            float bb[4] = {b.x, b.y, b.z, b.w};
#pragma unroll
            for (int i = 0; i < 8; i++)
#pragma unroll
                for (int j = 0; j < 4; j++) acc[i][j] += a[i] * bb[j];
        }
        __syncthreads();
    }

    float4 bias;
    bias.x = bih[n0 + tn + 0] + bhh[n0 + tn + 0];
    bias.y = bih[n0 + tn + 1] + bhh[n0 + tn + 1];
    bias.z = bih[n0 + tn + 2] + bhh[n0 + tn + 2];
    bias.w = bih[n0 + tn + 3] + bhh[n0 + tn + 3];
#pragma unroll
    for (int i = 0; i < 8; i++) {
        float4 o;
        o.x = acc[i][0] + bias.x;
        o.y = acc[i][1] + bias.y;
        o.z = acc[i][2] + bias.z;
        o.w = acc[i][3] + bias.w;
        *reinterpret_cast<float4*>(&C[(size_t)(m0 + tm + i) * N + n0 + tn]) = o;
    }
}

// ---------------- LSTM recurrence (gate-local threads, cluster DSMEM exchange) ----
// Grid: (BATCH/NB)*G CTAs of 128 threads; for G>1 launched as clusters of G.
// Each CTA owns hidden units [sl*JS, (sl+1)*JS) for batches [grp*NB, grp*NB+NB).
// Thread (j, bg) owns all 4 gates of hidden unit j for BB batches; c is in regs.
// Full h vector lives in double-buffered smem hs[2][NB][H]; for G>1 each CTA
// stores its computed h slice into every cluster peer's hs via st.shared::cluster,
// then one barrier.cluster per step.
template <int H, int G, int NB, int BB>
__global__ void __launch_bounds__(128) lstm_recur_kernel(
    const float* __restrict__ pre, const float* __restrict__ Whh,
    float* __restrict__ xout)
{
    constexpr int JS  = H / G;
    constexpr int NBG = NB / BB;
    static_assert(JS * NBG == 128, "thread mapping");

    extern __shared__ float sm[];
    float* Ws = sm;                   // [H][JS][4] : Ws[(k*JS+j)*4+gate]
    float* hs = Ws + H * JS * 4;      // [2][NB][H]

    const int tid   = threadIdx.x;
    const int j     = tid % JS;
    const int bg    = tid / JS;
    const int bbase = bg * BB;
    const int grp   = (G > 1) ? (blockIdx.x / G) : blockIdx.x;
    const int sl    = (G > 1) ? (blockIdx.x % G) : 0;
    const int b0    = grp * NB;
    const int j0    = sl * JS;

    // Load weight slice (coalesced global reads)
    for (int r = 0; r < 4 * JS; r++) {
        const int gate = r / JS, jj = r % JS;
        const float* src = Whh + (size_t)(gate * H + j0 + jj) * H;
        for (int k = tid; k < H; k += 128)
            Ws[(k * JS + jj) * 4 + gate] = src[k];
    }
    for (int i = tid; i < 2 * NB * H; i += 128) hs[i] = 0.f;
    __syncthreads();
    if (G > 1) cluster_sync_();   // peers' hs must be zeroed before anyone writes them

    float c[BB];
#pragma unroll
    for (int b = 0; b < BB; b++) c[b] = 0.f;

    const float* pb[BB];
    float* xo[BB];
#pragma unroll
    for (int b = 0; b < BB; b++) {
        pb[b] = pre + (size_t)(b0 + bbase + b) * SEQ * (4 * H) + j0 + j;
        xo[b] = xout + (size_t)(b0 + bbase + b) * SEQ * H + j0 + j;
    }

    // prefetch pre(t=0)
    float pin[BB][4];
#pragma unroll
    for (int b = 0; b < BB; b++)
#pragma unroll
        for (int g = 0; g < 4; g++) pin[b][g] = __ldcs(pb[b] + g * H);

    const float4* wsp = reinterpret_cast<const float4*>(Ws);

    for (int t = 0; t < SEQ; t++) {
        const float* rbuf = hs + (t & 1) * (NB * H);
        float*       wbuf = hs + ((t + 1) & 1) * (NB * H);

        float4 acc[BB];
#pragma unroll
        for (int b = 0; b < BB; b++) {
            acc[b].x = pin[b][0]; acc[b].y = pin[b][1];
            acc[b].z = pin[b][2]; acc[b].w = pin[b][3];
        }
        // prefetch pre(t+1) — consumed next step, hidden behind the dot loop
        {
            const int tn = (t + 1 < SEQ) ? t + 1 : t;
#pragma unroll
            for (int b = 0; b < BB; b++)
#pragma unroll
                for (int g = 0; g < 4; g++)
                    pin[b][g] = __ldcs(pb[b] + (size_t)tn * 4 * H + g * H);
        }

        // dot over H, software-pipelined in blocks of 4 k
        float4 hc[BB], wc[4];
#pragma unroll
        for (int b = 0; b < BB; b++)
            hc[b] = *reinterpret_cast<const float4*>(&rbuf[(bbase + b) * H]);
#pragma unroll
        for (int kk = 0; kk < 4; kk++) wc[kk] = wsp[kk * JS + j];

#pragma unroll 2
        for (int kb = 0; kb < H / 4; kb++) {
            float4 hn[BB], wn[4];
            const int k2 = (kb + 1 < H / 4) ? (kb + 1) * 4 : 0;
#pragma unroll
            for (int b = 0; b < BB; b++)
                hn[b] = *reinterpret_cast<const float4*>(&rbuf[(bbase + b) * H + k2]);
#pragma unroll
            for (int kk = 0; kk < 4; kk++) wn[kk] = wsp[(k2 + kk) * JS + j];

#pragma unroll
            for (int kk = 0; kk < 4; kk++) {
#pragma unroll
                for (int b = 0; b < BB; b++) {
                    const float hv = reinterpret_cast<const float*>(&hc[b])[kk];
                    acc[b].x += hv * wc[kk].x;
                    acc[b].y += hv * wc[kk].y;
                    acc[b].z += hv * wc[kk].z;
                    acc[b].w += hv * wc[kk].w;
                }
            }
#pragma unroll
            for (int b = 0; b < BB; b++) hc[b] = hn[b];
#pragma unroll
            for (int kk = 0; kk < 4; kk++) wc[kk] = wn[kk];
        }

        // activations (register-local; gate order i,f,g,o)
#pragma unroll
        for (int b = 0; b < BB; b++) {
            const float gi = sigf(acc[b].x);
            const float gf = sigf(acc[b].y);
            const float gg = tanhfast(acc[b].z);
            const float go = sigf(acc[b].w);
            c[b] = gf * c[b] + gi * gg;
            const float h = go * tanhfast(c[b]);
            xo[b][(size_t)t * H] = h;
            if (G == 1) {
                wbuf[(bbase + b) * H + j] = h;
            } else {
                const uint32_t la = smem_u32(&wbuf[(bbase + b) * H + j0 + j]);
#pragma unroll
                for (int dst = 0; dst < G; dst++) st_cluster_f32(la, dst, h);
            }
        }

        if (G == 1) __syncthreads();
        else        cluster_sync_();
    }
}

// ---------------- final linear (OUT_DIM=1) + tanh ----------------
__global__ void __launch_bounds__(256) final_kernel(
    const float* __restrict__ x3, const float* __restrict__ Wl,
    const float* __restrict__ bl, float* __restrict__ out)
{
    int warp = (blockIdx.x * 256 + threadIdx.x) >> 5;
    int lane = threadIdx.x & 31;
    const float* xr = x3 + (size_t)warp * H2;
    float acc = 0.f;
#pragma unroll
    for (int i = 0; i < 8; i++) {
        int k = i * 32 + lane;
        acc += xr[k] * __ldg(&Wl[k]);
    }
#pragma unroll
    for (int off = 16; off; off >>= 1) acc += __shfl_xor_sync(0xffffffffu, acc, off);
    if (lane == 0) out[warp] = tanhf(acc + bl[0]);
}

// ---------------- launch ----------------
template <typename KernT>
static void launch_cluster(KernT kern, int grid, int G, int smem,
                           const float* pre, const float* Whh, float* xout)
{
    cudaLaunchConfig_t cfg = {};
    cfg.gridDim = dim3(grid, 1, 1);
    cfg.blockDim = dim3(128, 1, 1);
    cfg.dynamicSmemBytes = smem;
    cfg.stream = 0;
    cudaLaunchAttribute attr[1];
    attr[0].id = cudaLaunchAttributeClusterDimension;
    attr[0].val.clusterDim.x = G;
    attr[0].val.clusterDim.y = 1;
    attr[0].val.clusterDim.z = 1;
    cfg.attrs = attr;
    cfg.numAttrs = 1;
    cudaLaunchKernelEx(&cfg, kern, pre, Whh, xout);
}

extern "C" void kernel_launch(void* const* d_in, const int* in_sizes, int n_in,
                              void* d_out, int out_size)
{
    const float* noise = (const float*)d_in[0];
    const float* Wih0 = (const float*)d_in[1];
    const float* Whh0 = (const float*)d_in[2];
    const float* bih0 = (const float*)d_in[3];
    const float* bhh0 = (const float*)d_in[4];
    const float* Wih1 = (const float*)d_in[5];
    const float* Whh1 = (const float*)d_in[6];
    const float* bih1 = (const float*)d_in[7];
    const float* bhh1 = (const float*)d_in[8];
    const float* Wih2 = (const float*)d_in[9];
    const float* Whh2 = (const float*)d_in[10];
    const float* bih2 = (const float*)d_in[11];
    const float* bhh2 = (const float*)d_in[12];
    const float* Wl   = (const float*)d_in[13];
    const float* bl   = (const float*)d_in[14];
    float* out = (float*)d_out;

    float *pre, *x1, *x2, *x3;
    cudaGetSymbolAddress((void**)&pre, g_pre);
    cudaGetSymbolAddress((void**)&x1,  g_x1);
    cudaGetSymbolAddress((void**)&x2,  g_x2);
    cudaGetSymbolAddress((void**)&x3,  g_x3);

    // smem bytes: (H*(H/G)*4 + 2*NB*H) * 4
    const int smem0 = (H0 * H0 * 4 + 2 * 2 * H0) * 4;       // 66,560
    const int smem1 = (H1 * (H1 / 2) * 4 + 2 * 4 * H1) * 4; // 135,168
    const int smem2 = (H2 * (H2 / 8) * 4 + 2 * 16 * H2) * 4; // 163,840

    cudaFuncSetAttribute(lstm_recur_kernel<H0, 1, 2, 1>,
                         cudaFuncAttributeMaxDynamicSharedMemorySize, smem0);
    cudaFuncSetAttribute(lstm_recur_kernel<H1, 2, 4, 2>,
                         cudaFuncAttributeMaxDynamicSharedMemorySize, smem1);
    cudaFuncSetAttribute(lstm_recur_kernel<H2, 8, 16, 4>,
                         cudaFuncAttributeMaxDynamicSharedMemorySize, smem2);

    const int MBLK = (BATCH * SEQ) / 128;  // 1024

    // Layer 0
    gemm_pre_kernel<INDIM, 4 * H0><<<dim3(MBLK, (4 * H0) / 64), 256>>>(noise, Wih0, bih0, bhh0, pre);
    lstm_recur_kernel<H0, 1, 2, 1><<<128, 128, smem0>>>(pre, Whh0, x1);

    // Layer 1
    gemm_pre_kernel<H0, 4 * H1><<<dim3(MBLK, (4 * H1) / 64), 256>>>(x1, Wih1, bih1, bhh1, pre);
    launch_cluster(lstm_recur_kernel<H1, 2, 4, 2>, 128, 2, smem1, pre, Whh1, x2);

    // Layer 2
    gemm_pre_kernel<H1, 4 * H2><<<dim3(MBLK, (4 * H2) / 64), 256>>>(x2, Wih2, bih2, bhh2, pre);
    launch_cluster(lstm_recur_kernel<H2, 8, 16, 4>, 128, 8, smem2, pre, Whh2, x3);

    // Final linear + tanh
    final_kernel<<<(BATCH * SEQ) / 8, 256>>>(x3, Wl, bl, out);
}